// round 14
// baseline (speedup 1.0000x reference)
#include <cuda_runtime.h>
#include <cuda_fp16.h>
#include <cstdint>

#define BB 16
#define LQ 2048
#define LK 2048
#define DD 512
#define TOPK 512

// ---------------------------------------------------------------------------
// Device-global scratch (no allocations allowed)
// ---------------------------------------------------------------------------
__device__ float  g_scores[(size_t)BB * LQ * LK];                 // approx, unscaled
__device__ float  g_rowinv[(size_t)BB * LQ];                      // per-row 1/Z
__device__ __half g_Qh[(size_t)BB * LQ * DD];                     // fp16(Q)
__device__ __half g_Kh[(size_t)BB * LK * DD];
__device__ __half g_Kl[(size_t)BB * LK * DD];
__device__ __half g_Vth[(size_t)BB * DD * LK];                    // V^T [b,d,k]
__device__ __half g_Vtl[(size_t)BB * DD * LK];
__device__ __half g_Ph[(size_t)BB * LQ * LK];                     // unnormalized exp

// ---------------------------------------------------------------------------
// PTX helpers
// ---------------------------------------------------------------------------
__device__ __forceinline__ uint32_t smem_u32(const void* p) {
    uint32_t a;
    asm("{ .reg .u64 t; cvta.to.shared.u64 t, %1; cvt.u32.u64 %0, t; }" : "=r"(a) : "l"(p));
    return a;
}
__device__ __forceinline__ void cp16(uint32_t s, const void* g) {
    asm volatile("cp.async.cg.shared.global [%0], [%1], 16;" :: "r"(s), "l"(g));
}
__device__ __forceinline__ void cp_commit() { asm volatile("cp.async.commit_group;" ::: "memory"); }
__device__ __forceinline__ void cp_wait0()  { asm volatile("cp.async.wait_group 0;" ::: "memory"); }
__device__ __forceinline__ void cp_wait1()  { asm volatile("cp.async.wait_group 1;" ::: "memory"); }
__device__ __forceinline__ void cp_wait2()  { asm volatile("cp.async.wait_group 2;" ::: "memory"); }

__device__ __forceinline__ void ldsm4(uint32_t* r, uint32_t addr) {
    asm volatile("ldmatrix.sync.aligned.m8n8.x4.shared.b16 {%0,%1,%2,%3}, [%4];"
                 : "=r"(r[0]), "=r"(r[1]), "=r"(r[2]), "=r"(r[3]) : "r"(addr));
}
__device__ __forceinline__ void mma_f16(float* c, const uint32_t* a, const uint32_t* b) {
    asm volatile("mma.sync.aligned.m16n8k16.row.col.f32.f16.f16.f32 "
                 "{%0,%1,%2,%3}, {%4,%5,%6,%7}, {%8,%9}, {%0,%1,%2,%3};"
                 : "+f"(c[0]), "+f"(c[1]), "+f"(c[2]), "+f"(c[3])
                 : "r"(a[0]), "r"(a[1]), "r"(a[2]), "r"(a[3]), "r"(b[0]), "r"(b[1]));
}

// ---------------------------------------------------------------------------
// 2-term HMMA GEMM: C = A * (Bh + Bl)^T  (A fp16, B fp16 hi/lo)
// Block tile 128x128, BK=32, 8 warps (64x32 warp tiles), 2 CTAs/SM,
// triple-buffered cp.async. SMEM per stage: A | Bh | Bl (24 KB).
// ---------------------------------------------------------------------------
#define MAT_BYTES 8192
#define BUF_BYTES (3 * MAT_BYTES)       // 24 KB
#define NSTAGE 3
#define GEMM_SMEM (NSTAGE * BUF_BYTES)  // 72 KB

__device__ __forceinline__ void load_buf(uint32_t sbase,
    const __half* __restrict__ A, long ldA,
    const __half* __restrict__ Bh, const __half* __restrict__ Bl, long ldB,
    int kk, int tid)
{
    const int r0 = tid >> 2;            // 0..63
    const int c  = tid & 3;
#pragma unroll
    for (int p = 0; p < 2; p++) {
        const int r = r0 + p * 64;
        const uint32_t soff = r * 64 + ((c ^ ((r >> 1) & 3)) << 4);
        const size_t goffA = (size_t)r * ldA + kk + c * 8;
        const size_t goffB = (size_t)r * ldB + kk + c * 8;
        cp16(sbase + soff,                 A  + goffA);
        cp16(sbase + MAT_BYTES + soff,     Bh + goffB);
        cp16(sbase + 2 * MAT_BYTES + soff, Bl + goffB);
    }
}

__global__ __launch_bounds__(256, 2)
void hmma_gemm(const __half* __restrict__ A, long ldA, long strideA,
               const __half* __restrict__ Bh, const __half* __restrict__ Bl,
               long ldB, long strideB,
               float* __restrict__ C, long ldC, long strideC, int Ktot,
               const float* __restrict__ rowScale)
{
    extern __shared__ char smem[];
    const uint32_t sbase = smem_u32(smem);

    const int tid  = threadIdx.x;
    const int lane = tid & 31, warp = tid >> 5;
    const int wm = (warp >> 2) * 64;
    const int wn = (warp & 3) * 32;
    const int b  = blockIdx.z;
    const int n0 = blockIdx.x * 128, m0 = blockIdx.y * 128;

    const __half* pA  = A  + (size_t)b * strideA + (size_t)m0 * ldA;
    const __half* pBh = Bh + (size_t)b * strideB + (size_t)n0 * ldB;
    const __half* pBl = Bl + (size_t)b * strideB + (size_t)n0 * ldB;

    const int aRow = (lane & 7) | (((lane >> 3) & 1) << 3);
    const int aCk  = (lane >> 4) & 1;
    const int bRow = (lane & 7) | (((lane >> 4) & 1) << 3);
    const int bCk  = (lane >> 3) & 1;

    float acc[4][4][4];
#pragma unroll
    for (int i = 0; i < 4; i++)
#pragma unroll
        for (int j = 0; j < 4; j++)
#pragma unroll
            for (int t = 0; t < 4; t++) acc[i][j][t] = 0.f;

    const int nc = Ktot / 32;

    load_buf(sbase, pA, ldA, pBh, pBl, ldB, 0, tid);
    cp_commit();
    if (nc > 1) {
        load_buf(sbase + BUF_BYTES, pA, ldA, pBh, pBl, ldB, 32, tid);
        cp_commit();
    }

    int stage = 0;
    for (int c = 0; c < nc; c++) {
        if (c + 2 < nc) {
            int ls = stage + 2; if (ls >= NSTAGE) ls -= NSTAGE;
            load_buf(sbase + ls * BUF_BYTES, pA, ldA, pBh, pBl, ldB, (c + 2) * 32, tid);
            cp_commit();
            cp_wait2();
        } else if (c + 1 < nc) {
            cp_wait1();
        } else {
            cp_wait0();
        }
        __syncthreads();

        const uint32_t bb = sbase + stage * BUF_BYTES;
#pragma unroll
        for (int s = 0; s < 2; s++) {
            uint32_t bh[2][4], bl[2][4];
#pragma unroll
            for (int np = 0; np < 2; np++) {
                const int r = wn + np * 16 + bRow;
                const int ck = s * 2 + bCk;
                const uint32_t off = r * 64 + ((ck ^ ((r >> 1) & 3)) << 4);
                ldsm4(bh[np], bb + MAT_BYTES + off);
                ldsm4(bl[np], bb + 2 * MAT_BYTES + off);
            }
#pragma unroll
            for (int mh = 0; mh < 2; mh++) {
                uint32_t ah[2][4];
#pragma unroll
                for (int mi = 0; mi < 2; mi++) {
                    const int r = wm + mh * 32 + mi * 16 + aRow;
                    const int ck = s * 2 + aCk;
                    const uint32_t off = r * 64 + ((ck ^ ((r >> 1) & 3)) << 4);
                    ldsm4(ah[mi], bb + off);
                }
#pragma unroll
                for (int mi = 0; mi < 2; mi++)
#pragma unroll
                    for (int nj = 0; nj < 4; nj++)
                        mma_f16(acc[mh * 2 + mi][nj], ah[mi], &bh[nj >> 1][(nj & 1) * 2]);
#pragma unroll
                for (int mi = 0; mi < 2; mi++)
#pragma unroll
                    for (int nj = 0; nj < 4; nj++)
                        mma_f16(acc[mh * 2 + mi][nj], ah[mi], &bl[nj >> 1][(nj & 1) * 2]);
            }
        }
        __syncthreads();
        if (++stage == NSTAGE) stage = 0;
    }

    const int g = lane >> 2, tg = lane & 3;
    float* Cb = C + (size_t)b * strideC;
    const float* rs = rowScale ? rowScale + (size_t)b * LQ : nullptr;
#pragma unroll
    for (int mi = 0; mi < 4; mi++) {
        const int row = m0 + wm + mi * 16 + g;
        const float sA = rs ? rs[row]     : 1.f;
        const float sB = rs ? rs[row + 8] : 1.f;
#pragma unroll
        for (int nj = 0; nj < 4; nj++) {
            const int col = n0 + wn + nj * 8 + tg * 2;
            *(float2*)(Cb + (size_t)row * ldC + col) =
                make_float2(acc[mi][nj][0] * sA, acc[mi][nj][1] * sA);
            *(float2*)(Cb + (size_t)(row + 8) * ldC + col) =
                make_float2(acc[mi][nj][2] * sB, acc[mi][nj][3] * sB);
        }
    }
}

// ---------------------------------------------------------------------------
// fp32 -> fp16 convert (hi only), 8 elems/thread
// ---------------------------------------------------------------------------
__global__ void tofp16_kernel(const float4* __restrict__ in,
                              __half* __restrict__ hi, int n8)
{
    int i = blockIdx.x * blockDim.x + threadIdx.x;
    if (i >= n8) return;
    float4 v0 = in[2 * i], v1 = in[2 * i + 1];
    float x[8] = { v0.x, v0.y, v0.z, v0.w, v1.x, v1.y, v1.z, v1.w };
    uint32_t hw[4];
#pragma unroll
    for (int j = 0; j < 4; j++) {
        hw[j] = (uint32_t)__half_as_ushort(__float2half_rn(x[2 * j]))
              | ((uint32_t)__half_as_ushort(__float2half_rn(x[2 * j + 1])) << 16);
    }
    *(uint4*)(hi + 8 * (size_t)i) = make_uint4(hw[0], hw[1], hw[2], hw[3]);
}

// ---------------------------------------------------------------------------
// fp32 -> (hi, lo) fp16 split, 8 elems/thread
// ---------------------------------------------------------------------------
__global__ void split_kernel(const float4* __restrict__ in,
                             __half* __restrict__ hi,
                             __half* __restrict__ lo, int n8)
{
    int i = blockIdx.x * blockDim.x + threadIdx.x;
    if (i >= n8) return;
    float4 v0 = in[2 * i], v1 = in[2 * i + 1];
    float x[8] = { v0.x, v0.y, v0.z, v0.w, v1.x, v1.y, v1.z, v1.w };
    uint32_t hw[4], lw[4];
#pragma unroll
    for (int j = 0; j < 4; j++) {
        __half ha = __float2half_rn(x[2 * j]);
        __half hb = __float2half_rn(x[2 * j + 1]);
        __half la = __float2half_rn(x[2 * j] - __half2float(ha));
        __half lb = __float2half_rn(x[2 * j + 1] - __half2float(hb));
        hw[j] = (uint32_t)__half_as_ushort(ha) | ((uint32_t)__half_as_ushort(hb) << 16);
        lw[j] = (uint32_t)__half_as_ushort(la) | ((uint32_t)__half_as_ushort(lb) << 16);
    }
    *(uint4*)(hi + 8 * (size_t)i) = make_uint4(hw[0], hw[1], hw[2], hw[3]);
    *(uint4*)(lo + 8 * (size_t)i) = make_uint4(lw[0], lw[1], lw[2], lw[3]);
}

// ---------------------------------------------------------------------------
// Transpose V [b,k,d] -> Vt [b,d,k], split hi/lo fp16
// ---------------------------------------------------------------------------
__global__ __launch_bounds__(256)
void vt_split(const float* __restrict__ V)
{
    __shared__ float tile[64][33];
    const int b = blockIdx.z;
    const int k0 = blockIdx.x * 64, d0 = blockIdx.y * 32;
    const int tid = threadIdx.x;
    const float* Vb = V + (size_t)b * LK * DD;

    const int lx = tid & 31, lr = tid >> 5;
#pragma unroll
    for (int r = lr; r < 64; r += 8)
        tile[r][lx] = Vb[(size_t)(k0 + r) * DD + d0 + lx];
    __syncthreads();

    const int rr = tid >> 3;
    const int kc = (tid & 7) * 8;
    uint32_t hw[4], lw[4];
#pragma unroll
    for (int j = 0; j < 4; j++) {
        float xa = tile[kc + 2 * j][rr];
        float xb = tile[kc + 2 * j + 1][rr];
        __half ha = __float2half_rn(xa), hb = __float2half_rn(xb);
        __half la = __float2half_rn(xa - __half2float(ha));
        __half lb = __float2half_rn(xb - __half2float(hb));
        hw[j] = (uint32_t)__half_as_ushort(ha) | ((uint32_t)__half_as_ushort(hb) << 16);
        lw[j] = (uint32_t)__half_as_ushort(la) | ((uint32_t)__half_as_ushort(lb) << 16);
    }
    size_t o = (size_t)b * DD * LK + (size_t)(d0 + rr) * LK + k0 + kc;
    *(uint4*)(g_Vth + o) = make_uint4(hw[0], hw[1], hw[2], hw[3]);
    *(uint4*)(g_Vtl + o) = make_uint4(lw[0], lw[1], lw[2], lw[3]);
}

// ---------------------------------------------------------------------------
// Top-k + sparse softmax with EXACT boundary repair.
// Approx scores (2-term QK) select everything except a small band around
// tau~; band members get exact fp32 dot-product scores and exact ranking.
// ---------------------------------------------------------------------------
__device__ __forceinline__ unsigned fkey(float x) {
    unsigned u = __float_as_uint(x);
    return u ^ ((u >> 31) ? 0xFFFFFFFFu : 0x80000000u);
}
__device__ __forceinline__ float fkey_inv(unsigned u) {
    unsigned bits = (u >> 31) ? (u ^ 0x80000000u) : ~u;
    return __uint_as_float(bits);
}

#define CAND_CAP 1024
#define BAND_CAP 64
#define SM_SCALE 0.04419417382415922f   // 1/sqrt(512)
#define BIN_INVW 2.0f
#define MARGIN   0.08f                  // ~20 sigma of the 2-term score error

__device__ __forceinline__ void select_bin(const unsigned* hist, int k,
                                           int* ps_bin, int* ps_k,
                                           int lane, int wid)
{
    if (wid == 0) {
        unsigned h[8], tot = 0;
#pragma unroll
        for (int j = 0; j < 8; j++) { h[j] = hist[lane * 8 + j]; tot += h[j]; }
        unsigned suf = tot;
#pragma unroll
        for (int o = 1; o < 32; o <<= 1) {
            unsigned v = __shfl_down_sync(0xFFFFFFFFu, suf, o);
            if (lane + o < 32) suf += v;
        }
        unsigned run = suf - tot;
        for (int j = 7; j >= 0; j--) {
            unsigned cge = run + h[j];
            if (cge >= (unsigned)k && run < (unsigned)k) {
                *ps_bin = lane * 8 + j;
                *ps_k = k - (int)run;
            }
            run = cge;
        }
    }
}

__device__ __forceinline__ float radix_select_dev(const float* arr, int n, int k,
                                                  unsigned* hist, int* ps_bin, int* ps_k,
                                                  int tid, int lane, int wid)
{
    unsigned prefix = 0;
#pragma unroll
    for (int pass = 0; pass < 4; pass++) {
        const int shift = 24 - pass * 8;
        const unsigned mask = pass ? (0xFFFFFFFFu << (32 - 8 * pass)) : 0u;
        if (tid < 256) hist[tid] = 0;
        __syncthreads();
        for (int i = tid; i < n; i += 256) {
            unsigned u = fkey(arr[i]);
            if ((u & mask) == prefix)
                atomicAdd(&hist[(u >> shift) & 0xFF], 1u);
        }
        __syncthreads();
        select_bin(hist, k, ps_bin, ps_k, lane, wid);
        __syncthreads();
        prefix |= ((unsigned)*ps_bin) << shift;
        k = *ps_k;
        __syncthreads();
    }
    return fkey_inv(prefix);
}

__global__ __launch_bounds__(256)
void topk_softmax(const float* __restrict__ Qf, const float* __restrict__ Kf)
{
    __shared__ float row[LK];                 // 8 KB (approx scores)
    __shared__ float qrow[DD];                // 2 KB (exact Q row)
    __shared__ float cand[CAND_CAP];          // 4 KB
    __shared__ unsigned char flags[LK];       // 2 KB (bins, then select flags)
    __shared__ float sx[BAND_CAP];
    __shared__ int   bidx[BAND_CAP];
    __shared__ unsigned char selb[BAND_CAP];
    __shared__ unsigned hist[256];
    __shared__ float redf[8];
    __shared__ int   redi[8];
    __shared__ float s_bcast;
    __shared__ int s_bin, s_k, s_band, s_nab;

    const int tid = threadIdx.x;
    const int lane = tid & 31, wid = tid >> 5;
    const int r = blockIdx.x;
    const int bb = r >> 11;                   // r / LQ
    const float* Srow = g_scores + (size_t)r * LK;
    const float* Qrow = Qf + (size_t)r * DD;
    const float* Kb   = Kf + (size_t)bb * LK * DD;
    __half* PhR = g_Ph + (size_t)r * LK;

    if (tid == 0) { s_band = 0; }

    // ---- scan 1: load + rowmax ----
    float m = -3.4e38f;
    for (int i = tid; i < LK / 4; i += 256) {
        float4 v = ((const float4*)Srow)[i];
        ((float4*)row)[i] = v;
        m = fmaxf(fmaxf(m, v.x), fmaxf(v.y, v.z));
        m = fmaxf(m, v.w);
    }
#pragma unroll
    for (int o = 16; o > 0; o >>= 1) m = fmaxf(m, __shfl_xor_sync(0xFFFFFFFFu, m, o));
    if (lane == 0) redf[wid] = m;
    __syncthreads();
    if (tid == 0) {
        float mm = redf[0];
#pragma unroll
        for (int i = 1; i < 8; i++) mm = fmaxf(mm, redf[i]);
        s_bcast = mm;
    }
    if (tid < 256) hist[tid] = 0;
    __syncthreads();
    const float rowmax = s_bcast;

    // ---- scan 2: linear-bucket histogram + cached bins ----
    for (int i = tid; i < LK; i += 256) {
        int bin = (int)((rowmax - row[i]) * BIN_INVW);
        bin = (bin > 255) ? 255 : bin;
        flags[i] = (unsigned char)bin;
        atomicAdd(&hist[255 - bin], 1u);
    }
    __syncthreads();
    select_bin(hist, TOPK, &s_bin, &s_k, lane, wid);
    __syncthreads();
    const int rb = 255 - s_bin;
    const int kk = s_k;
    if (tid == 0) s_band = 0;                 // (reset; reused below)
    __syncthreads();

    // ---- scan 3: compact bucket candidates for tau~ ----
    for (int i = tid; i < LK; i += 256) {
        if (flags[i] == (unsigned char)rb) {
            int idx = atomicAdd(&s_band, 1);
            if (idx < CAND_CAP) cand[idx] = row[i];
        }
    }
    __syncthreads();
    const int ncand = s_band;
    const bool uselist = (rb != 255) && (ncand <= CAND_CAP);
    __syncthreads();

    float tau_a;
    if (uselist)
        tau_a = radix_select_dev(cand, ncand, kk, hist, &s_bin, &s_k, tid, lane, wid);
    else
        tau_a = radix_select_dev(row, LK, TOPK, hist, &s_bin, &s_k, tid, lane, wid);

    // ---- boundary repair: exact selection inside [tau~ - M, tau~ + M] ----
    const float hib = tau_a + MARGIN, lob = tau_a - MARGIN;
    if (tid == 0) s_band = 0;
    __syncthreads();
    int myab = 0;
    for (int i = tid; i < LK; i += 256) {
        float x = row[i];
        if (x > hib) myab++;
        else if (x >= lob) {
            int j = atomicAdd(&s_band, 1);
            if (j < BAND_CAP) bidx[j] = i;
        }
    }
#pragma unroll
    for (int o = 16; o > 0; o >>= 1) myab += __shfl_xor_sync(0xFFFFFFFFu, myab, o);
    if (lane == 0) redi[wid] = myab;
    __syncthreads();
    if (tid == 0) {
        int t = 0;
#pragma unroll
        for (int i = 0; i < 8; i++) t += redi[i];
        s_nab = t;
    }
    __syncthreads();
    const int nab = s_nab;
    const int nband = s_band;

    if (nband <= BAND_CAP && nab < TOPK) {
        // exact fp32 scores for band members
        for (int i = tid; i < DD; i += 256) qrow[i] = Qrow[i];
        __syncthreads();
        for (int j = wid; j < nband; j += 8) {
            const float* Kr = Kb + (size_t)bidx[j] * DD;
            float s = 0.f;
            for (int d = lane; d < DD; d += 32) s += qrow[d] * Kr[d];
#pragma unroll
            for (int o = 16; o > 0; o >>= 1) s += __shfl_xor_sync(0xFFFFFFFFu, s, o);
            if (lane == 0) sx[j] = s;
        }
        __syncthreads();
        const int kprime = TOPK - nab;
        if (tid < nband) {
            float v = sx[tid];
            int rank = 0;
            for (int j = 0; j < nband; j++) rank += (sx[j] > v);
            selb[tid] = (rank < kprime) ? 1 : 0;
        }
        __syncthreads();
        for (int i = tid; i < LK; i += 256) flags[i] = (row[i] > hib) ? 1 : 0;
        __syncthreads();
        if (tid < nband) flags[bidx[tid]] = selb[tid];
    } else {
        // degenerate fallback: approx threshold selection
        for (int i = tid; i < LK; i += 256) flags[i] = (row[i] >= tau_a) ? 1 : 0;
    }
    __syncthreads();

    // ---- scan 4: unnormalized exp (fp16, vectorized) + sum ----
    float ssum = 0.f;
    for (int i = tid; i < LK / 4; i += 256) {
        float4 v = ((const float4*)row)[i];
        uchar4 f = ((const uchar4*)flags)[i];
        float p0 = f.x ? __expf((v.x - rowmax) * SM_SCALE) : 0.f;
        float p1 = f.y ? __expf((v.y - rowmax) * SM_SCALE) : 0.f;
        float p2 = f.z ? __expf((v.z - rowmax) * SM_SCALE) : 0.f;
        float p3 = f.w ? __expf((v.w - rowmax) * SM_SCALE) : 0.f;
        ssum += (p0 + p1) + (p2 + p3);
        uint2 hv;
        hv.x = (uint32_t)__half_as_ushort(__float2half_rn(p0))
             | ((uint32_t)__half_as_ushort(__float2half_rn(p1)) << 16);
        hv.y = (uint32_t)__half_as_ushort(__float2half_rn(p2))
             | ((uint32_t)__half_as_ushort(__float2half_rn(p3)) << 16);
        ((uint2*)PhR)[i] = hv;
    }
#pragma unroll
    for (int o = 16; o > 0; o >>= 1) ssum += __shfl_xor_sync(0xFFFFFFFFu, ssum, o);
    if (lane == 0) redf[wid] = ssum;
    __syncthreads();
    if (tid == 0) {
        float t = 0.f;
#pragma unroll
        for (int i = 0; i < 8; i++) t += redf[i];
        g_rowinv[r] = 1.0f / t;
    }
}

// ---------------------------------------------------------------------------
extern "C" void kernel_launch(void* const* d_in, const int* in_sizes, int n_in,
                              void* d_out, int out_size)
{
    const float* Q = (const float*)d_in[0];
    const float* K = (const float*)d_in[1];
    const float* V = (const float*)d_in[2];
    float* O = (float*)d_out;

    cudaFuncSetAttribute(hmma_gemm, cudaFuncAttributeMaxDynamicSharedMemorySize, GEMM_SMEM);

    void *pQh, *pKh, *pKl, *pVth, *pVtl, *pPh, *pS, *pRI;
    cudaGetSymbolAddress(&pQh, g_Qh);
    cudaGetSymbolAddress(&pKh, g_Kh);   cudaGetSymbolAddress(&pKl, g_Kl);
    cudaGetSymbolAddress(&pVth, g_Vth); cudaGetSymbolAddress(&pVtl, g_Vtl);
    cudaGetSymbolAddress(&pPh, g_Ph);
    cudaGetSymbolAddress(&pS, g_scores);
    cudaGetSymbolAddress(&pRI, g_rowinv);

    const int n8 = (BB * LQ * DD) / 8;

    tofp16_kernel<<<(n8 + 255) / 256, 256>>>((const float4*)Q, (__half*)pQh, n8);
    split_kernel<<<(n8 + 255) / 256, 256>>>((const float4*)K,
        (__half*)pKh, (__half*)pKl, n8);

    vt_split<<<dim3(LK / 64, DD / 32, BB), 256>>>(V);

    // approx scores = Qh @ (Kh+Kl)^T   (2-term, unscaled)
    hmma_gemm<<<dim3(LK / 128, LQ / 128, BB), 256, GEMM_SMEM>>>(
        (const __half*)pQh, DD, (long)LQ * DD,
        (const __half*)pKh, (const __half*)pKl, DD, (long)LK * DD,
        (float*)pS, LK, (long)LQ * LK, DD, nullptr);

    topk_softmax<<<BB * LQ, 256>>>(Q, K);

    // O = diag(1/Z) * (Ph @ (Vh+Vl))   (V pre-transposed to [b,d,k])
    hmma_gemm<<<dim3(DD / 128, LQ / 128, BB), 256, GEMM_SMEM>>>(
        (const __half*)pPh, LK, (long)LQ * LK,
        (const __half*)pVth, (const __half*)pVtl, LK, (long)DD * LK,
        O, DD, (long)LQ * DD, LK, (const float*)pRI);
}